// round 13
// baseline (speedup 1.0000x reference)
#include <cuda_runtime.h>
#include <cuda_fp16.h>
#include <cstdint>
#include <math.h>

#define BN_WIN 4096
#define NTOK   64
#define DIMC   384
#define NHEAD  12
#define HEADD  32
#define QKVD   1152
#define MTOT   (BN_WIN * NTOK)   // 262144

// ---------------- scratch (device globals) ----------------------------------
// g_qkvh layout: [b][sec][h][tok][d] = ((b*3+sec)*12+h)*2048 + tok*32 + d
__device__ __half g_qkvh[(size_t)MTOT * QKVD];
__device__ __half g_xh[(size_t)MTOT * DIMC];      // fp16 x (row-major)
__device__ __half g_ah[(size_t)MTOT * DIMC];      // fp16 attention out (row-major)
__device__ __half g_wqh[QKVD * DIMC];
__device__ __half g_wph[DIMC * DIMC];
__device__ float  g_biasx[NHEAD * NTOK * NTOK];   // expanded rel-pos bias

// ---------------- helpers ----------------------------------------------------
__device__ __forceinline__ uint32_t smem_u32(const void* p) {
    uint32_t a;
    asm("{ .reg .u64 t; cvta.to.shared.u64 t, %1; cvt.u32.u64 %0, t; }" : "=r"(a) : "l"(p));
    return a;
}
__device__ __forceinline__ void ldsm_x4(uint32_t* r, uint32_t addr) {
    asm volatile("ldmatrix.sync.aligned.m8n8.x4.shared.b16 {%0,%1,%2,%3}, [%4];"
        : "=r"(r[0]), "=r"(r[1]), "=r"(r[2]), "=r"(r[3]) : "r"(addr));
}
__device__ __forceinline__ void ldsm_x4_t(uint32_t* r, uint32_t addr) {
    asm volatile("ldmatrix.sync.aligned.m8n8.x4.trans.shared.b16 {%0,%1,%2,%3}, [%4];"
        : "=r"(r[0]), "=r"(r[1]), "=r"(r[2]), "=r"(r[3]) : "r"(addr));
}
__device__ __forceinline__ void mma_f16(float* d, const uint32_t* a, const uint32_t* b) {
    asm volatile("mma.sync.aligned.m16n8k16.row.col.f32.f16.f16.f32 "
        "{%0,%1,%2,%3}, {%4,%5,%6,%7}, {%8,%9}, {%0,%1,%2,%3};"
        : "+f"(d[0]), "+f"(d[1]), "+f"(d[2]), "+f"(d[3])
        : "r"(a[0]), "r"(a[1]), "r"(a[2]), "r"(a[3]), "r"(b[0]), "r"(b[1]));
}
__device__ __forceinline__ uint32_t pack_h2(float lo, float hi) {
    __half2 p = __floats2half2_rn(lo, hi);
    return *(uint32_t*)&p;
}
#define CP_ASYNC16(dst, src) \
    asm volatile("cp.async.cg.shared.global [%0], [%1], 16;" :: "r"(dst), "l"(src) : "memory")
#define CP_COMMIT()  asm volatile("cp.async.commit_group;" ::: "memory")
#define CP_WAIT0()   asm volatile("cp.async.wait_group 0;" ::: "memory")

// ---------------------------------------------------------------------------
// HMMA NT GEMM (fp16 in): C[M,N] = A[M,K] @ B[N,K]^T + bias[N]
// Block 128x64, 4 warps (2m x 2n, warp tile 64x32 — proven shape), k-step 32,
// 2-stage cp.async double buffer, ONE barrier per k-step, XOR swizzle.
// 4 CTAs/SM = 16 warps/SM in 4 independent barrier domains (desynchronized
// LDSM/HMMA phases keep the tensor pipe fed).
// BLOCKED_OUT=true: scatter fp16 into head-blocked QKV layout (64-col tiles).
// grid.x = N/64, grid.y = M/128. K % 32 == 0.
// ---------------------------------------------------------------------------
__device__ __forceinline__ void load_stage(
    const __half* Ab, const __half* Bb, int K, int k0,
    uint32_t sAdst, uint32_t sBdst, int t)
{
    // A: 128 rows x 32 cols, 4 chunks per thread (one row each)
    {
        const int row = t;
        const __half* ga = Ab + (size_t)row * K + k0;
#pragma unroll
        for (int c = 0; c < 4; c++) {
            int sw = c ^ ((row >> 1) & 3);
            CP_ASYNC16(sAdst + row * 64 + sw * 16, ga + c * 8);
        }
    }
    // B: 64 rows x 32 cols, 2 chunks per thread
    {
        const int row = t >> 1, qb = (t & 1) * 2;
        const __half* gb = Bb + (size_t)row * K + k0 + qb * 8;
#pragma unroll
        for (int c = 0; c < 2; c++) {
            int chunk = qb + c;
            int sw = chunk ^ ((row >> 1) & 3);
            CP_ASYNC16(sBdst + row * 64 + sw * 16, gb + c * 8);
        }
    }
}

template <typename OutT, bool BLOCKED_OUT>
__global__ __launch_bounds__(128, 4) void hmma_gemm(
    const __half* __restrict__ A, const __half* __restrict__ B,
    const float* __restrict__ bias, OutT* __restrict__ C, int K, int ldc)
{
    __shared__ __align__(16) __half sA[2][128 * 32];
    __shared__ __align__(16) __half sB[2][64 * 32];

    const int t = threadIdx.x, wid = t >> 5, lane = t & 31;
    const int bm = blockIdx.y, bn = blockIdx.x;
    const __half* Ab = A + (size_t)bm * 128 * K;
    const __half* Bb = B + (size_t)bn * 64 * K;
    const uint32_t sA0 = smem_u32(sA), sB0 = smem_u32(sB);
    const int wm = (wid >> 1) * 64, wn = (wid & 1) * 32;
    const int nstg = K >> 5;

    float acc[4][4][4];
#pragma unroll
    for (int mt = 0; mt < 4; mt++)
#pragma unroll
        for (int nt = 0; nt < 4; nt++)
#pragma unroll
            for (int r = 0; r < 4; r++) acc[mt][nt][r] = 0.0f;

    load_stage(Ab, Bb, K, 0, sA0, sB0, t);
    CP_COMMIT();

    for (int s = 0; s < nstg; s++) {
        CP_WAIT0();
        __syncthreads();   // single barrier: also orders compute(s-1) before overwrite below
        if (s + 1 < nstg) {
            int buf = (s + 1) & 1;
            load_stage(Ab, Bb, K, (s + 1) * 32, sA0 + buf * 8192, sB0 + buf * 4096, t);
            CP_COMMIT();
        }
        const uint32_t ab = sA0 + (s & 1) * 8192;
        const uint32_t bb = sB0 + (s & 1) * 4096;
#pragma unroll
        for (int h = 0; h < 2; h++) {
            uint32_t a[4][4], b[4][2];
#pragma unroll
            for (int mt = 0; mt < 4; mt++) {
                int row = wm + mt * 16 + (lane & 15);
                int chunk = 2 * h + (lane >> 4);
                int sw = chunk ^ ((row >> 1) & 3);
                ldsm_x4(a[mt], ab + row * 64 + sw * 16);
            }
#pragma unroll
            for (int p = 0; p < 2; p++) {
                int row = wn + p * 16 + ((lane >> 4) << 3) + (lane & 7);
                int chunk = 2 * h + ((lane >> 3) & 1);
                int sw = chunk ^ ((row >> 1) & 3);
                uint32_t r4[4];
                ldsm_x4(r4, bb + row * 64 + sw * 16);
                b[p * 2][0] = r4[0]; b[p * 2][1] = r4[1];
                b[p * 2 + 1][0] = r4[2]; b[p * 2 + 1][1] = r4[3];
            }
#pragma unroll
            for (int mt = 0; mt < 4; mt++)
#pragma unroll
                for (int nt = 0; nt < 4; nt++)
                    mma_f16(acc[mt][nt], a[mt], b[nt]);
        }
    }

    if constexpr (BLOCKED_OUT) {
        // QKV scatter: 64-col tile bn covers sec = bn/6, heads (bn%6)*2 + 0..1
        const int sec = bn / 6;
        const int hbase = (bn % 6) * 2;
#pragma unroll
        for (int mt = 0; mt < 4; mt++) {
            const int r0 = bm * 128 + wm + mt * 16 + (lane >> 2);
            const int b0 = r0 >> 6, tok = r0 & 63;
#pragma unroll
            for (int nt = 0; nt < 4; nt++) {
                const int cit = wn + nt * 8 + ((lane & 3) << 1);   // 0..63
                const int hh = hbase + (cit >> 5), d = cit & 31;
                float2 bv = *(const float2*)(bias + bn * 64 + cit);
                __half* blk = (__half*)C + (((size_t)b0 * 3 + sec) * 12 + hh) * 2048;
                __half2 h0 = __floats2half2_rn(acc[mt][nt][0] + bv.x, acc[mt][nt][1] + bv.y);
                __half2 h1 = __floats2half2_rn(acc[mt][nt][2] + bv.x, acc[mt][nt][3] + bv.y);
                *(__half2*)(blk + tok * 32 + d) = h0;
                *(__half2*)(blk + (tok + 8) * 32 + d) = h1;
            }
        }
    } else {
#pragma unroll
        for (int mt = 0; mt < 4; mt++) {
            const int r0 = bm * 128 + wm + mt * 16 + (lane >> 2);
#pragma unroll
            for (int nt = 0; nt < 4; nt++) {
                const int col = bn * 64 + wn + nt * 8 + ((lane & 3) << 1);
                float2 bv = *(const float2*)(bias + col);
                float* p0 = (float*)C + (size_t)r0 * ldc + col;
                float2 o0, o1;
                o0.x = acc[mt][nt][0] + bv.x; o0.y = acc[mt][nt][1] + bv.y;
                o1.x = acc[mt][nt][2] + bv.x; o1.y = acc[mt][nt][3] + bv.y;
                *(float2*)p0 = o0;
                *(float2*)(p0 + 8 * (size_t)ldc) = o1;
            }
        }
    }
}

// ---------------------------------------------------------------------------
// Fused prep: cvt x / qkv_w / proj_w to fp16 + expand rel-pos bias (1 launch)
// ---------------------------------------------------------------------------
#define N4X  (MTOT * DIMC / 4)
#define N4WQ (QKVD * DIMC / 4)
#define N4WP (DIMC * DIMC / 4)
#define NBX  (NHEAD * NTOK * NTOK)
#define PREP_TOT (N4X + N4WQ + N4WP + NBX)

__device__ __forceinline__ void cvt4(const float4* in, __half* out, int i) {
    float4 v = in[i];
    __half2 a = __floats2half2_rn(v.x, v.y);
    __half2 b = __floats2half2_rn(v.z, v.w);
    uint2 o;
    o.x = *(uint32_t*)&a;
    o.y = *(uint32_t*)&b;
    *(uint2*)(out + (size_t)i * 4) = o;
}

__global__ __launch_bounds__(256) void prep_kernel(
    const float* __restrict__ x, const float* __restrict__ qkv_w,
    const float* __restrict__ proj_w, const float* __restrict__ bt)
{
    int idx = blockIdx.x * 256 + threadIdx.x;
    if (idx < N4X) {
        cvt4((const float4*)x, g_xh, idx);
    } else if (idx < N4X + N4WQ) {
        cvt4((const float4*)qkv_w, g_wqh, idx - N4X);
    } else if (idx < N4X + N4WQ + N4WP) {
        cvt4((const float4*)proj_w, g_wph, idx - N4X - N4WQ);
    } else if (idx < PREP_TOT) {
        int e = idx - N4X - N4WQ - N4WP;
        int h = e >> 12;
        int i = (e >> 6) & 63;
        int j = e & 63;
        int ri = i >> 3, ci = i & 7, rj = j >> 3, cj = j & 7;
        g_biasx[e] = bt[((ri - rj + 7) * 15 + (ci - cj + 7)) * 12 + h];
    }
}

// ---------------------------------------------------------------------------
// HMMA window attention. Block = (window, 4-head group), 4 warps, 1 warp/head.
// Reads head-blocked g_qkvh (contiguous 4KB per (sec,head)) -> coalesced.
// ---------------------------------------------------------------------------
__global__ __launch_bounds__(128) void attn_hmma()
{
    __shared__ __align__(16) __half sm[4][3][2048];   // [warp][q/k/v][64*32]

    const int b = blockIdx.x;
    const int w = threadIdx.x >> 5, lane = threadIdx.x & 31;
    const int h = blockIdx.y * 4 + w;

    {
        const __half* base = g_qkvh + (((size_t)b * 3) * 12 + h) * 2048;
#pragma unroll
        for (int sec = 0; sec < 3; sec++) {
            const __half* g = base + sec * (12 * 2048);
            char* dst = (char*)sm[w][sec];
#pragma unroll
            for (int it = 0; it < 8; it++) {
                int e = it * 32 + lane;
                int row = e >> 2, seg = e & 3;
                uint4 val = *(const uint4*)(g + e * 8);
                int sw = seg ^ ((row >> 1) & 3);
                *(uint4*)(dst + row * 64 + sw * 16) = val;
            }
        }
    }
    __syncwarp();

    const uint32_t qs = smem_u32(sm[w][0]);
    const uint32_t ks = smem_u32(sm[w][1]);
    const uint32_t vs = smem_u32(sm[w][2]);

    uint32_t aq[4][2][4];
#pragma unroll
    for (int mt = 0; mt < 4; mt++)
#pragma unroll
        for (int kd = 0; kd < 2; kd++) {
            int row = mt * 16 + (lane & 15);
            int chunk = kd * 2 + (lane >> 4);
            int sw = chunk ^ ((row >> 1) & 3);
            ldsm_x4(aq[mt][kd], qs + row * 64 + sw * 16);
        }

    uint32_t bk[8][2][2];
#pragma unroll
    for (int np = 0; np < 4; np++)
#pragma unroll
        for (int kd = 0; kd < 2; kd++) {
            int row = np * 16 + ((lane >> 4) << 3) + (lane & 7);
            int chunk = kd * 2 + ((lane >> 3) & 1);
            int sw = chunk ^ ((row >> 1) & 3);
            uint32_t r4[4];
            ldsm_x4(r4, ks + row * 64 + sw * 16);
            bk[np * 2][kd][0] = r4[0];     bk[np * 2][kd][1] = r4[1];
            bk[np * 2 + 1][kd][0] = r4[2]; bk[np * 2 + 1][kd][1] = r4[3];
        }

    float s[4][8][4];
#pragma unroll
    for (int mt = 0; mt < 4; mt++)
#pragma unroll
        for (int nt = 0; nt < 8; nt++) {
            s[mt][nt][0] = s[mt][nt][1] = s[mt][nt][2] = s[mt][nt][3] = 0.0f;
#pragma unroll
            for (int kd = 0; kd < 2; kd++)
                mma_f16(s[mt][nt], aq[mt][kd], bk[nt][kd]);
        }

    const float scale = 0.17677669529663687f;
    const float* bb = g_biasx + (size_t)h * NTOK * NTOK;
    const int rA = lane >> 2, c0 = (lane & 3) * 2;
#pragma unroll
    for (int mt = 0; mt < 4; mt++) {
        int rowA = mt * 16 + rA;
#pragma unroll
        for (int nt = 0; nt < 8; nt++) {
            float2 bA = *(const float2*)(bb + rowA * 64 + nt * 8 + c0);
            float2 bB = *(const float2*)(bb + (rowA + 8) * 64 + nt * 8 + c0);
            s[mt][nt][0] = fmaf(s[mt][nt][0], scale, bA.x);
            s[mt][nt][1] = fmaf(s[mt][nt][1], scale, bA.y);
            s[mt][nt][2] = fmaf(s[mt][nt][2], scale, bB.x);
            s[mt][nt][3] = fmaf(s[mt][nt][3], scale, bB.y);
        }
    }

    float invA[4], invB[4];
#pragma unroll
    for (int mt = 0; mt < 4; mt++) {
        float mA = -1e30f, mB = -1e30f;
#pragma unroll
        for (int nt = 0; nt < 8; nt++) {
            mA = fmaxf(mA, fmaxf(s[mt][nt][0], s[mt][nt][1]));
            mB = fmaxf(mB, fmaxf(s[mt][nt][2], s[mt][nt][3]));
        }
        mA = fmaxf(mA, __shfl_xor_sync(0xffffffffu, mA, 1));
        mA = fmaxf(mA, __shfl_xor_sync(0xffffffffu, mA, 2));
        mB = fmaxf(mB, __shfl_xor_sync(0xffffffffu, mB, 1));
        mB = fmaxf(mB, __shfl_xor_sync(0xffffffffu, mB, 2));
        float sA = 0.0f, sB = 0.0f;
#pragma unroll
        for (int nt = 0; nt < 8; nt++) {
            s[mt][nt][0] = __expf(s[mt][nt][0] - mA);
            s[mt][nt][1] = __expf(s[mt][nt][1] - mA);
            s[mt][nt][2] = __expf(s[mt][nt][2] - mB);
            s[mt][nt][3] = __expf(s[mt][nt][3] - mB);
            sA += s[mt][nt][0] + s[mt][nt][1];
            sB += s[mt][nt][2] + s[mt][nt][3];
        }
        sA += __shfl_xor_sync(0xffffffffu, sA, 1);
        sA += __shfl_xor_sync(0xffffffffu, sA, 2);
        sB += __shfl_xor_sync(0xffffffffu, sB, 1);
        sB += __shfl_xor_sync(0xffffffffu, sB, 2);
        invA[mt] = 1.0f / sA;
        invB[mt] = 1.0f / sB;
    }

    uint32_t bv[4][4][2];
#pragma unroll
    for (int kt = 0; kt < 4; kt++)
#pragma unroll
        for (int np = 0; np < 2; np++) {
            int row = kt * 16 + (lane & 15);
            int chunk = np * 2 + (lane >> 4);
            int sw = chunk ^ ((row >> 1) & 3);
            uint32_t r4[4];
            ldsm_x4_t(r4, vs + row * 64 + sw * 16);
            bv[kt][np * 2][0] = r4[0];     bv[kt][np * 2][1] = r4[1];
            bv[kt][np * 2 + 1][0] = r4[2]; bv[kt][np * 2 + 1][1] = r4[3];
        }

    __half* obase = g_ah + (size_t)(b * NTOK) * DIMC + h * HEADD;
#pragma unroll
    for (int mt = 0; mt < 4; mt++) {
        uint32_t p[4][4];
#pragma unroll
        for (int kt = 0; kt < 4; kt++) {
            p[kt][0] = pack_h2(s[mt][2 * kt][0], s[mt][2 * kt][1]);
            p[kt][1] = pack_h2(s[mt][2 * kt][2], s[mt][2 * kt][3]);
            p[kt][2] = pack_h2(s[mt][2 * kt + 1][0], s[mt][2 * kt + 1][1]);
            p[kt][3] = pack_h2(s[mt][2 * kt + 1][2], s[mt][2 * kt + 1][3]);
        }
        float o[4][4];
#pragma unroll
        for (int nt = 0; nt < 4; nt++) {
            o[nt][0] = o[nt][1] = o[nt][2] = o[nt][3] = 0.0f;
#pragma unroll
            for (int kt = 0; kt < 4; kt++)
                mma_f16(o[nt], p[kt], bv[kt][nt]);
        }
        int rowA = mt * 16 + rA;
#pragma unroll
        for (int nt = 0; nt < 4; nt++) {
            int col = nt * 8 + c0;
            __half2 hA = __floats2half2_rn(o[nt][0] * invA[mt], o[nt][1] * invA[mt]);
            __half2 hB = __floats2half2_rn(o[nt][2] * invB[mt], o[nt][3] * invB[mt]);
            *(__half2*)(obase + (size_t)rowA * DIMC + col) = hA;
            *(__half2*)(obase + (size_t)(rowA + 8) * DIMC + col) = hB;
        }
    }
}

// ---------------------------------------------------------------------------
// Launch. Inputs: x, qkv_w, qkv_b, proj_w, proj_b, bias_table
// ---------------------------------------------------------------------------
extern "C" void kernel_launch(void* const* d_in, const int* in_sizes, int n_in,
                              void* d_out, int out_size)
{
    const float* x          = (const float*)d_in[0];
    const float* qkv_w      = (const float*)d_in[1];
    const float* qkv_b      = (const float*)d_in[2];
    const float* proj_w     = (const float*)d_in[3];
    const float* proj_b     = (const float*)d_in[4];
    const float* bias_table = (const float*)d_in[5];
    float* out = (float*)d_out;

    __half *qkvh, *xh, *ah, *wqh, *wph;
    cudaGetSymbolAddress((void**)&qkvh, g_qkvh);
    cudaGetSymbolAddress((void**)&xh, g_xh);
    cudaGetSymbolAddress((void**)&ah, g_ah);
    cudaGetSymbolAddress((void**)&wqh, g_wqh);
    cudaGetSymbolAddress((void**)&wph, g_wph);

    // 0) fused prep (single launch)
    prep_kernel<<<(PREP_TOT + 255) / 256, 256>>>(x, qkv_w, proj_w, bias_table);

    // 1) QKV GEMM -> head-blocked fp16 g_qkvh   (K=384)
    {
        dim3 grid(QKVD / 64, MTOT / 128);   // (18, 2048)
        hmma_gemm<__half, true><<<grid, 128>>>(xh, wqh, qkv_b, qkvh, DIMC, 0);
    }

    // 2) HMMA attention -> fp16 g_ah
    {
        dim3 grid(BN_WIN, NHEAD / 4);        // (4096, 3)
        attn_hmma<<<grid, 128>>>();
    }

    // 3) proj GEMM -> fp32 out   (K=384)
    {
        dim3 grid(DIMC / 64, MTOT / 128);   // (6, 2048)
        hmma_gemm<float, false><<<grid, 128>>>(ah, wph, proj_b, out, DIMC, DIMC);
    }
}

// round 14
// speedup vs baseline: 1.2951x; 1.2951x over previous
#include <cuda_runtime.h>
#include <cuda_fp16.h>
#include <cstdint>
#include <math.h>

#define BN_WIN 4096
#define NTOK   64
#define DIMC   384
#define NHEAD  12
#define HEADD  32
#define QKVD   1152
#define MTOT   (BN_WIN * NTOK)   // 262144

// ---------------- scratch (device globals) ----------------------------------
// g_qkvh layout: [b][sec][h][tok][d] = ((b*3+sec)*12+h)*2048 + tok*32 + d
__device__ __half g_qkvh[(size_t)MTOT * QKVD];
__device__ __half g_xh[(size_t)MTOT * DIMC];      // fp16 x (row-major)
__device__ __half g_ah[(size_t)MTOT * DIMC];      // fp16 attention out (row-major)
__device__ __half g_wqh[QKVD * DIMC];
__device__ __half g_wph[DIMC * DIMC];
__device__ float  g_biasx[NHEAD * NTOK * NTOK];   // expanded rel-pos bias

// ---------------- helpers ----------------------------------------------------
__device__ __forceinline__ uint32_t smem_u32(const void* p) {
    uint32_t a;
    asm("{ .reg .u64 t; cvta.to.shared.u64 t, %1; cvt.u32.u64 %0, t; }" : "=r"(a) : "l"(p));
    return a;
}
__device__ __forceinline__ void ldsm_x4(uint32_t* r, uint32_t addr) {
    asm volatile("ldmatrix.sync.aligned.m8n8.x4.shared.b16 {%0,%1,%2,%3}, [%4];"
        : "=r"(r[0]), "=r"(r[1]), "=r"(r[2]), "=r"(r[3]) : "r"(addr));
}
__device__ __forceinline__ void ldsm_x4_t(uint32_t* r, uint32_t addr) {
    asm volatile("ldmatrix.sync.aligned.m8n8.x4.trans.shared.b16 {%0,%1,%2,%3}, [%4];"
        : "=r"(r[0]), "=r"(r[1]), "=r"(r[2]), "=r"(r[3]) : "r"(addr));
}
__device__ __forceinline__ void mma_f16(float* d, const uint32_t* a, const uint32_t* b) {
    asm volatile("mma.sync.aligned.m16n8k16.row.col.f32.f16.f16.f32 "
        "{%0,%1,%2,%3}, {%4,%5,%6,%7}, {%8,%9}, {%0,%1,%2,%3};"
        : "+f"(d[0]), "+f"(d[1]), "+f"(d[2]), "+f"(d[3])
        : "r"(a[0]), "r"(a[1]), "r"(a[2]), "r"(a[3]), "r"(b[0]), "r"(b[1]));
}
__device__ __forceinline__ uint32_t pack_h2(float lo, float hi) {
    __half2 p = __floats2half2_rn(lo, hi);
    return *(uint32_t*)&p;
}
#define CP_ASYNC16(dst, src) \
    asm volatile("cp.async.cg.shared.global [%0], [%1], 16;" :: "r"(dst), "l"(src) : "memory")
#define CP_COMMIT()  asm volatile("cp.async.commit_group;" ::: "memory")
#define CP_WAIT0()   asm volatile("cp.async.wait_group 0;" ::: "memory")

// ---------------------------------------------------------------------------
// HMMA NT GEMM (fp16 in): C[M,N] = A[M,K] @ B[N,K]^T + bias[N]
// Block 128x128, 8 warps (2x4, warp tile 64x32 — proven), K-STEP 64
// (halves barrier count, doubles ILP window), 2-stage double buffer via
// 64 KB dynamic smem, swizzle chunk^(row&7) for 128B rows.
// grid.x = N/128, grid.y = M/128. K % 64 == 0.
// ---------------------------------------------------------------------------
#define GSTEP   64
#define STAGE_A 16384              // 128 rows * 128 B
#define STAGE_B 16384
#define STAGE_SZ (STAGE_A + STAGE_B)   // 32 KB
#define GEMM_SMEM (2 * STAGE_SZ)       // 64 KB

__device__ __forceinline__ void load_stage(
    const __half* Ab, const __half* Bb, int K, int k0,
    uint32_t sAdst, uint32_t sBdst, int t)
{
    const int row  = t >> 1;
    const int half = t & 1;            // which 64B half of the 128B row
    const __half* ga = Ab + (size_t)row * K + k0 + half * 32;
    const __half* gb = Bb + (size_t)row * K + k0 + half * 32;
#pragma unroll
    for (int c = 0; c < 4; c++) {
        int chunk = half * 4 + c;
        int sw = chunk ^ (row & 7);
        CP_ASYNC16(sAdst + row * 128 + sw * 16, ga + c * 8);
        CP_ASYNC16(sBdst + row * 128 + sw * 16, gb + c * 8);
    }
}

template <typename OutT, bool BLOCKED_OUT>
__global__ __launch_bounds__(256, 2) void hmma_gemm(
    const __half* __restrict__ A, const __half* __restrict__ B,
    const float* __restrict__ bias, OutT* __restrict__ C, int K, int ldc)
{
    extern __shared__ __align__(16) char smem[];

    const int t = threadIdx.x, wid = t >> 5, lane = t & 31;
    const int bm = blockIdx.y, bn = blockIdx.x;
    const __half* Ab = A + (size_t)bm * 128 * K;
    const __half* Bb = B + (size_t)bn * 128 * K;
    const uint32_t s0 = smem_u32(smem);
    const int wm = (wid >> 2) * 64, wn = (wid & 3) * 32;
    const int nstg = K / GSTEP;

    float acc[4][4][4];
#pragma unroll
    for (int mt = 0; mt < 4; mt++)
#pragma unroll
        for (int nt = 0; nt < 4; nt++)
#pragma unroll
            for (int r = 0; r < 4; r++) acc[mt][nt][r] = 0.0f;

    load_stage(Ab, Bb, K, 0, s0, s0 + STAGE_A, t);
    CP_COMMIT();

    for (int s = 0; s < nstg; s++) {
        CP_WAIT0();
        __syncthreads();
        if (s + 1 < nstg) {
            uint32_t nb = s0 + ((s + 1) & 1) * STAGE_SZ;
            load_stage(Ab, Bb, K, (s + 1) * GSTEP, nb, nb + STAGE_A, t);
            CP_COMMIT();
        }
        const uint32_t ab = s0 + (s & 1) * STAGE_SZ;
        const uint32_t bb = ab + STAGE_A;
#pragma unroll
        for (int kd = 0; kd < 4; kd++) {   // four k16 steps per stage
            uint32_t a[4][4], b[4][2];
#pragma unroll
            for (int mt = 0; mt < 4; mt++) {
                int row = wm + mt * 16 + (lane & 15);
                int chunk = kd * 2 + (lane >> 4);
                int sw = chunk ^ (row & 7);
                ldsm_x4(a[mt], ab + row * 128 + sw * 16);
            }
#pragma unroll
            for (int p = 0; p < 2; p++) {
                int row = wn + p * 16 + ((lane >> 4) << 3) + (lane & 7);
                int chunk = kd * 2 + ((lane >> 3) & 1);
                int sw = chunk ^ (row & 7);
                uint32_t r4[4];
                ldsm_x4(r4, bb + row * 128 + sw * 16);
                b[p * 2][0] = r4[0]; b[p * 2][1] = r4[1];
                b[p * 2 + 1][0] = r4[2]; b[p * 2 + 1][1] = r4[3];
            }
#pragma unroll
            for (int mt = 0; mt < 4; mt++)
#pragma unroll
                for (int nt = 0; nt < 4; nt++)
                    mma_f16(acc[mt][nt], a[mt], b[nt]);
        }
        __syncthreads();
    }

    if constexpr (BLOCKED_OUT) {
        // QKV scatter: 128-col tile bn covers sec = bn/3, heads (bn%3)*4 + 0..3
        const int sec = bn / 3;
        const int hbase = (bn % 3) * 4;
#pragma unroll
        for (int mt = 0; mt < 4; mt++) {
            const int r0 = bm * 128 + wm + mt * 16 + (lane >> 2);
            const int b0 = r0 >> 6, tok = r0 & 63;
#pragma unroll
            for (int nt = 0; nt < 4; nt++) {
                const int cit = wn + nt * 8 + ((lane & 3) << 1);   // 0..127
                const int hh = hbase + (cit >> 5), d = cit & 31;
                float2 bv = *(const float2*)(bias + bn * 128 + cit);
                __half* blk = (__half*)C + (((size_t)b0 * 3 + sec) * 12 + hh) * 2048;
                __half2 h0 = __floats2half2_rn(acc[mt][nt][0] + bv.x, acc[mt][nt][1] + bv.y);
                __half2 h1 = __floats2half2_rn(acc[mt][nt][2] + bv.x, acc[mt][nt][3] + bv.y);
                *(__half2*)(blk + tok * 32 + d) = h0;
                *(__half2*)(blk + (tok + 8) * 32 + d) = h1;
            }
        }
    } else {
#pragma unroll
        for (int mt = 0; mt < 4; mt++) {
            const int r0 = bm * 128 + wm + mt * 16 + (lane >> 2);
#pragma unroll
            for (int nt = 0; nt < 4; nt++) {
                const int col = bn * 128 + wn + nt * 8 + ((lane & 3) << 1);
                float2 bv = *(const float2*)(bias + col);
                float* p0 = (float*)C + (size_t)r0 * ldc + col;
                float2 o0, o1;
                o0.x = acc[mt][nt][0] + bv.x; o0.y = acc[mt][nt][1] + bv.y;
                o1.x = acc[mt][nt][2] + bv.x; o1.y = acc[mt][nt][3] + bv.y;
                *(float2*)p0 = o0;
                *(float2*)(p0 + 8 * (size_t)ldc) = o1;
            }
        }
    }
}

// ---------------------------------------------------------------------------
// Fused prep: cvt x / qkv_w / proj_w to fp16 + expand rel-pos bias (1 launch)
// ---------------------------------------------------------------------------
#define N4X  (MTOT * DIMC / 4)
#define N4WQ (QKVD * DIMC / 4)
#define N4WP (DIMC * DIMC / 4)
#define NBX  (NHEAD * NTOK * NTOK)
#define PREP_TOT (N4X + N4WQ + N4WP + NBX)

__device__ __forceinline__ void cvt4(const float4* in, __half* out, int i) {
    float4 v = in[i];
    __half2 a = __floats2half2_rn(v.x, v.y);
    __half2 b = __floats2half2_rn(v.z, v.w);
    uint2 o;
    o.x = *(uint32_t*)&a;
    o.y = *(uint32_t*)&b;
    *(uint2*)(out + (size_t)i * 4) = o;
}

__global__ __launch_bounds__(256) void prep_kernel(
    const float* __restrict__ x, const float* __restrict__ qkv_w,
    const float* __restrict__ proj_w, const float* __restrict__ bt)
{
    int idx = blockIdx.x * 256 + threadIdx.x;
    if (idx < N4X) {
        cvt4((const float4*)x, g_xh, idx);
    } else if (idx < N4X + N4WQ) {
        cvt4((const float4*)qkv_w, g_wqh, idx - N4X);
    } else if (idx < N4X + N4WQ + N4WP) {
        cvt4((const float4*)proj_w, g_wph, idx - N4X - N4WQ);
    } else if (idx < PREP_TOT) {
        int e = idx - N4X - N4WQ - N4WP;
        int h = e >> 12;
        int i = (e >> 6) & 63;
        int j = e & 63;
        int ri = i >> 3, ci = i & 7, rj = j >> 3, cj = j & 7;
        g_biasx[e] = bt[((ri - rj + 7) * 15 + (ci - cj + 7)) * 12 + h];
    }
}

// ---------------------------------------------------------------------------
// HMMA window attention. Block = (window, 4-head group), 4 warps, 1 warp/head.
// Reads head-blocked g_qkvh (contiguous 4KB per (sec,head)) -> coalesced.
// ---------------------------------------------------------------------------
__global__ __launch_bounds__(128) void attn_hmma()
{
    __shared__ __align__(16) __half sm[4][3][2048];   // [warp][q/k/v][64*32]

    const int b = blockIdx.x;
    const int w = threadIdx.x >> 5, lane = threadIdx.x & 31;
    const int h = blockIdx.y * 4 + w;

    {
        const __half* base = g_qkvh + (((size_t)b * 3) * 12 + h) * 2048;
#pragma unroll
        for (int sec = 0; sec < 3; sec++) {
            const __half* g = base + sec * (12 * 2048);
            char* dst = (char*)sm[w][sec];
#pragma unroll
            for (int it = 0; it < 8; it++) {
                int e = it * 32 + lane;
                int row = e >> 2, seg = e & 3;
                uint4 val = *(const uint4*)(g + e * 8);
                int sw = seg ^ ((row >> 1) & 3);
                *(uint4*)(dst + row * 64 + sw * 16) = val;
            }
        }
    }
    __syncwarp();

    const uint32_t qs = smem_u32(sm[w][0]);
    const uint32_t ks = smem_u32(sm[w][1]);
    const uint32_t vs = smem_u32(sm[w][2]);

    uint32_t aq[4][2][4];
#pragma unroll
    for (int mt = 0; mt < 4; mt++)
#pragma unroll
        for (int kd = 0; kd < 2; kd++) {
            int row = mt * 16 + (lane & 15);
            int chunk = kd * 2 + (lane >> 4);
            int sw = chunk ^ ((row >> 1) & 3);
            ldsm_x4(aq[mt][kd], qs + row * 64 + sw * 16);
        }

    uint32_t bk[8][2][2];
#pragma unroll
    for (int np = 0; np < 4; np++)
#pragma unroll
        for (int kd = 0; kd < 2; kd++) {
            int row = np * 16 + ((lane >> 4) << 3) + (lane & 7);
            int chunk = kd * 2 + ((lane >> 3) & 1);
            int sw = chunk ^ ((row >> 1) & 3);
            uint32_t r4[4];
            ldsm_x4(r4, ks + row * 64 + sw * 16);
            bk[np * 2][kd][0] = r4[0];     bk[np * 2][kd][1] = r4[1];
            bk[np * 2 + 1][kd][0] = r4[2]; bk[np * 2 + 1][kd][1] = r4[3];
        }

    float s[4][8][4];
#pragma unroll
    for (int mt = 0; mt < 4; mt++)
#pragma unroll
        for (int nt = 0; nt < 8; nt++) {
            s[mt][nt][0] = s[mt][nt][1] = s[mt][nt][2] = s[mt][nt][3] = 0.0f;
#pragma unroll
            for (int kd = 0; kd < 2; kd++)
                mma_f16(s[mt][nt], aq[mt][kd], bk[nt][kd]);
        }

    const float scale = 0.17677669529663687f;
    const float* bb = g_biasx + (size_t)h * NTOK * NTOK;
    const int rA = lane >> 2, c0 = (lane & 3) * 2;
#pragma unroll
    for (int mt = 0; mt < 4; mt++) {
        int rowA = mt * 16 + rA;
#pragma unroll
        for (int nt = 0; nt < 8; nt++) {
            float2 bA = *(const float2*)(bb + rowA * 64 + nt * 8 + c0);
            float2 bB = *(const float2*)(bb + (rowA + 8) * 64 + nt * 8 + c0);
            s[mt][nt][0] = fmaf(s[mt][nt][0], scale, bA.x);
            s[mt][nt][1] = fmaf(s[mt][nt][1], scale, bA.y);
            s[mt][nt][2] = fmaf(s[mt][nt][2], scale, bB.x);
            s[mt][nt][3] = fmaf(s[mt][nt][3], scale, bB.y);
        }
    }

    float invA[4], invB[4];
#pragma unroll
    for (int mt = 0; mt < 4; mt++) {
        float mA = -1e30f, mB = -1e30f;
#pragma unroll
        for (int nt = 0; nt < 8; nt++) {
            mA = fmaxf(mA, fmaxf(s[mt][nt][0], s[mt][nt][1]));
            mB = fmaxf(mB, fmaxf(s[mt][nt][2], s[mt][nt][3]));
        }
        mA = fmaxf(mA, __shfl_xor_sync(0xffffffffu, mA, 1));
        mA = fmaxf(mA, __shfl_xor_sync(0xffffffffu, mA, 2));
        mB = fmaxf(mB, __shfl_xor_sync(0xffffffffu, mB, 1));
        mB = fmaxf(mB, __shfl_xor_sync(0xffffffffu, mB, 2));
        float sA = 0.0f, sB = 0.0f;
#pragma unroll
        for (int nt = 0; nt < 8; nt++) {
            s[mt][nt][0] = __expf(s[mt][nt][0] - mA);
            s[mt][nt][1] = __expf(s[mt][nt][1] - mA);
            s[mt][nt][2] = __expf(s[mt][nt][2] - mB);
            s[mt][nt][3] = __expf(s[mt][nt][3] - mB);
            sA += s[mt][nt][0] + s[mt][nt][1];
            sB += s[mt][nt][2] + s[mt][nt][3];
        }
        sA += __shfl_xor_sync(0xffffffffu, sA, 1);
        sA += __shfl_xor_sync(0xffffffffu, sA, 2);
        sB += __shfl_xor_sync(0xffffffffu, sB, 1);
        sB += __shfl_xor_sync(0xffffffffu, sB, 2);
        invA[mt] = 1.0f / sA;
        invB[mt] = 1.0f / sB;
    }

    uint32_t bv[4][4][2];
#pragma unroll
    for (int kt = 0; kt < 4; kt++)
#pragma unroll
        for (int np = 0; np < 2; np++) {
            int row = kt * 16 + (lane & 15);
            int chunk = np * 2 + (lane >> 4);
            int sw = chunk ^ ((row >> 1) & 3);
            uint32_t r4[4];
            ldsm_x4_t(r4, vs + row * 64 + sw * 16);
            bv[kt][np * 2][0] = r4[0];     bv[kt][np * 2][1] = r4[1];
            bv[kt][np * 2 + 1][0] = r4[2]; bv[kt][np * 2 + 1][1] = r4[3];
        }

    __half* obase = g_ah + (size_t)(b * NTOK) * DIMC + h * HEADD;
#pragma unroll
    for (int mt = 0; mt < 4; mt++) {
        uint32_t p[4][4];
#pragma unroll
        for (int kt = 0; kt < 4; kt++) {
            p[kt][0] = pack_h2(s[mt][2 * kt][0], s[mt][2 * kt][1]);
            p[kt][1] = pack_h2(s[mt][2 * kt][2], s[mt][2 * kt][3]);
            p[kt][2] = pack_h2(s[mt][2 * kt + 1][0], s[mt][2 * kt + 1][1]);
            p[kt][3] = pack_h2(s[mt][2 * kt + 1][2], s[mt][2 * kt + 1][3]);
        }
        float o[4][4];
#pragma unroll
        for (int nt = 0; nt < 4; nt++) {
            o[nt][0] = o[nt][1] = o[nt][2] = o[nt][3] = 0.0f;
#pragma unroll
            for (int kt = 0; kt < 4; kt++)
                mma_f16(o[nt], p[kt], bv[kt][nt]);
        }
        int rowA = mt * 16 + rA;
#pragma unroll
        for (int nt = 0; nt < 4; nt++) {
            int col = nt * 8 + c0;
            __half2 hA = __floats2half2_rn(o[nt][0] * invA[mt], o[nt][1] * invA[mt]);
            __half2 hB = __floats2half2_rn(o[nt][2] * invB[mt], o[nt][3] * invB[mt]);
            *(__half2*)(obase + (size_t)rowA * DIMC + col) = hA;
            *(__half2*)(obase + (size_t)(rowA + 8) * DIMC + col) = hB;
        }
    }
}

// ---------------------------------------------------------------------------
// Launch. Inputs: x, qkv_w, qkv_b, proj_w, proj_b, bias_table
// ---------------------------------------------------------------------------
extern "C" void kernel_launch(void* const* d_in, const int* in_sizes, int n_in,
                              void* d_out, int out_size)
{
    const float* x          = (const float*)d_in[0];
    const float* qkv_w      = (const float*)d_in[1];
    const float* qkv_b      = (const float*)d_in[2];
    const float* proj_w     = (const float*)d_in[3];
    const float* proj_b     = (const float*)d_in[4];
    const float* bias_table = (const float*)d_in[5];
    float* out = (float*)d_out;

    __half *qkvh, *xh, *ah, *wqh, *wph;
    cudaGetSymbolAddress((void**)&qkvh, g_qkvh);
    cudaGetSymbolAddress((void**)&xh, g_xh);
    cudaGetSymbolAddress((void**)&ah, g_ah);
    cudaGetSymbolAddress((void**)&wqh, g_wqh);
    cudaGetSymbolAddress((void**)&wph, g_wph);

    cudaFuncSetAttribute(hmma_gemm<__half, true>,
                         cudaFuncAttributeMaxDynamicSharedMemorySize, GEMM_SMEM);
    cudaFuncSetAttribute(hmma_gemm<float, false>,
                         cudaFuncAttributeMaxDynamicSharedMemorySize, GEMM_SMEM);

    // 0) fused prep (single launch)
    prep_kernel<<<(PREP_TOT + 255) / 256, 256>>>(x, qkv_w, proj_w, bias_table);

    // 1) QKV GEMM -> head-blocked fp16 g_qkvh   (K=384)
    {
        dim3 grid(QKVD / 128, MTOT / 128);   // (9, 2048)
        hmma_gemm<__half, true><<<grid, 256, GEMM_SMEM>>>(xh, wqh, qkv_b, qkvh, DIMC, 0);
    }

    // 2) HMMA attention -> fp16 g_ah
    {
        dim3 grid(BN_WIN, NHEAD / 4);        // (4096, 3)
        attn_hmma<<<grid, 128>>>();
    }

    // 3) proj GEMM -> fp32 out   (K=384)
    {
        dim3 grid(DIMC / 128, MTOT / 128);   // (3, 2048)
        hmma_gemm<float, false><<<grid, 256, GEMM_SMEM>>>(ah, wph, proj_b, out, DIMC, DIMC);
    }
}

// round 15
// speedup vs baseline: 1.3279x; 1.0254x over previous
#include <cuda_runtime.h>
#include <cuda_fp16.h>
#include <cstdint>
#include <math.h>

#define BN_WIN 4096
#define NTOK   64
#define DIMC   384
#define NHEAD  12
#define HEADD  32
#define QKVD   1152
#define MTOT   (BN_WIN * NTOK)   // 262144

// ---------------- scratch (device globals) ----------------------------------
// g_qkvh layout: [b][sec][h][tok][d] = ((b*3+sec)*12+h)*2048 + tok*32 + d
__device__ __half g_qkvh[(size_t)MTOT * QKVD];
__device__ __half g_xh[(size_t)MTOT * DIMC];      // fp16 x (row-major)
__device__ __half g_ah[(size_t)MTOT * DIMC];      // fp16 attention out (row-major)
__device__ __half g_wqh[QKVD * DIMC];
__device__ __half g_wph[DIMC * DIMC];
__device__ float  g_biasx[NHEAD * NTOK * NTOK];   // expanded rel-pos bias

// ---------------- helpers ----------------------------------------------------
__device__ __forceinline__ uint32_t smem_u32(const void* p) {
    uint32_t a;
    asm("{ .reg .u64 t; cvta.to.shared.u64 t, %1; cvt.u32.u64 %0, t; }" : "=r"(a) : "l"(p));
    return a;
}
__device__ __forceinline__ void ldsm_x4(uint32_t* r, uint32_t addr) {
    asm volatile("ldmatrix.sync.aligned.m8n8.x4.shared.b16 {%0,%1,%2,%3}, [%4];"
        : "=r"(r[0]), "=r"(r[1]), "=r"(r[2]), "=r"(r[3]) : "r"(addr));
}
__device__ __forceinline__ void ldsm_x4_t(uint32_t* r, uint32_t addr) {
    asm volatile("ldmatrix.sync.aligned.m8n8.x4.trans.shared.b16 {%0,%1,%2,%3}, [%4];"
        : "=r"(r[0]), "=r"(r[1]), "=r"(r[2]), "=r"(r[3]) : "r"(addr));
}
__device__ __forceinline__ void mma_f16(float* d, const uint32_t* a, const uint32_t* b) {
    asm volatile("mma.sync.aligned.m16n8k16.row.col.f32.f16.f16.f32 "
        "{%0,%1,%2,%3}, {%4,%5,%6,%7}, {%8,%9}, {%0,%1,%2,%3};"
        : "+f"(d[0]), "+f"(d[1]), "+f"(d[2]), "+f"(d[3])
        : "r"(a[0]), "r"(a[1]), "r"(a[2]), "r"(a[3]), "r"(b[0]), "r"(b[1]));
}
__device__ __forceinline__ uint32_t pack_h2(float lo, float hi) {
    __half2 p = __floats2half2_rn(lo, hi);
    return *(uint32_t*)&p;
}
#define CP_ASYNC16(dst, src) \
    asm volatile("cp.async.cg.shared.global [%0], [%1], 16;" :: "r"(dst), "l"(src) : "memory")
#define CP_COMMIT()  asm volatile("cp.async.commit_group;" ::: "memory")
#define CP_WAIT0()   asm volatile("cp.async.wait_group 0;" ::: "memory")

// ---------------------------------------------------------------------------
// HMMA NT GEMM (fp16 in): C[M,N] = A[M,K] @ B[N,K]^T + bias[N]
// Block 128x128, 8 warps (2x4, warp tile 64x32), K-STEP 64 (4 k16 sub-steps),
// 2-stage smem double buffer (64 KB dynamic) + REGISTER-DOUBLE-BUFFERED
// fragments: LDSM for kd+1 issues before the HMMAs of kd, hiding LDSM latency
// under tensor work for 3 of 4 sub-steps per stage.
// grid.x = N/128, grid.y = M/128. K % 64 == 0.
// ---------------------------------------------------------------------------
#define GSTEP   64
#define STAGE_A 16384              // 128 rows * 128 B
#define STAGE_B 16384
#define STAGE_SZ (STAGE_A + STAGE_B)   // 32 KB
#define GEMM_SMEM (2 * STAGE_SZ)       // 64 KB

__device__ __forceinline__ void load_stage(
    const __half* Ab, const __half* Bb, int K, int k0,
    uint32_t sAdst, uint32_t sBdst, int t)
{
    const int row  = t >> 1;
    const int half = t & 1;            // which 64B half of the 128B row
    const __half* ga = Ab + (size_t)row * K + k0 + half * 32;
    const __half* gb = Bb + (size_t)row * K + k0 + half * 32;
#pragma unroll
    for (int c = 0; c < 4; c++) {
        int chunk = half * 4 + c;
        int sw = chunk ^ (row & 7);
        CP_ASYNC16(sAdst + row * 128 + sw * 16, ga + c * 8);
        CP_ASYNC16(sBdst + row * 128 + sw * 16, gb + c * 8);
    }
}

template <typename OutT, bool BLOCKED_OUT>
__global__ __launch_bounds__(256, 2) void hmma_gemm(
    const __half* __restrict__ A, const __half* __restrict__ B,
    const float* __restrict__ bias, OutT* __restrict__ C, int K, int ldc)
{
    extern __shared__ __align__(16) char smem[];

    const int t = threadIdx.x, wid = t >> 5, lane = t & 31;
    const int bm = blockIdx.y, bn = blockIdx.x;
    const __half* Ab = A + (size_t)bm * 128 * K;
    const __half* Bb = B + (size_t)bn * 128 * K;
    const uint32_t s0 = smem_u32(smem);
    const int wm = (wid >> 2) * 64, wn = (wid & 3) * 32;
    const int nstg = K / GSTEP;

    // per-thread LDSM addressing (row-dependent parts, kd-independent)
    int arow[4], aoff[4];
#pragma unroll
    for (int mt = 0; mt < 4; mt++) {
        arow[mt] = wm + mt * 16 + (lane & 15);
        aoff[mt] = arow[mt] * 128;
    }
    int brow[2], boff[2];
#pragma unroll
    for (int p = 0; p < 2; p++) {
        brow[p] = wn + p * 16 + ((lane >> 4) << 3) + (lane & 7);
        boff[p] = brow[p] * 128;
    }
    const int achk = lane >> 4;          // +0/+1 within kd pair
    const int bchk = (lane >> 3) & 1;

    float acc[4][4][4];
#pragma unroll
    for (int mt = 0; mt < 4; mt++)
#pragma unroll
        for (int nt = 0; nt < 4; nt++)
#pragma unroll
            for (int r = 0; r < 4; r++) acc[mt][nt][r] = 0.0f;

    load_stage(Ab, Bb, K, 0, s0, s0 + STAGE_A, t);
    CP_COMMIT();

    uint32_t fa[2][4][4], fb[2][4][2];

#define LOADF(buf, ab_, bb_, kd_) do {                                         \
        _Pragma("unroll")                                                      \
        for (int mt = 0; mt < 4; mt++) {                                       \
            int sw = ((kd_) * 2 + achk) ^ (arow[mt] & 7);                      \
            ldsm_x4(fa[buf][mt], (ab_) + aoff[mt] + sw * 16);                  \
        }                                                                      \
        _Pragma("unroll")                                                      \
        for (int p = 0; p < 2; p++) {                                          \
            int sw = ((kd_) * 2 + bchk) ^ (brow[p] & 7);                       \
            uint32_t r4[4];                                                    \
            ldsm_x4(r4, (bb_) + boff[p] + sw * 16);                            \
            fb[buf][p * 2][0] = r4[0];     fb[buf][p * 2][1] = r4[1];          \
            fb[buf][p * 2 + 1][0] = r4[2]; fb[buf][p * 2 + 1][1] = r4[3];      \
        }                                                                      \
    } while (0)

    for (int s = 0; s < nstg; s++) {
        CP_WAIT0();
        __syncthreads();
        if (s + 1 < nstg) {
            uint32_t nb = s0 + ((s + 1) & 1) * STAGE_SZ;
            load_stage(Ab, Bb, K, (s + 1) * GSTEP, nb, nb + STAGE_A, t);
            CP_COMMIT();
        }
        const uint32_t ab = s0 + (s & 1) * STAGE_SZ;
        const uint32_t bb = ab + STAGE_A;

        LOADF(0, ab, bb, 0);
#pragma unroll
        for (int kd = 0; kd < 4; kd++) {
            const int cur = kd & 1;
            if (kd < 3) LOADF(cur ^ 1, ab, bb, kd + 1);
#pragma unroll
            for (int mt = 0; mt < 4; mt++)
#pragma unroll
                for (int nt = 0; nt < 4; nt++)
                    mma_f16(acc[mt][nt], fa[cur][mt], fb[cur][nt]);
        }
        __syncthreads();
    }
#undef LOADF

    if constexpr (BLOCKED_OUT) {
        // QKV scatter: 128-col tile bn covers sec = bn/3, heads (bn%3)*4 + 0..3
        const int sec = bn / 3;
        const int hbase = (bn % 3) * 4;
#pragma unroll
        for (int mt = 0; mt < 4; mt++) {
            const int r0 = bm * 128 + wm + mt * 16 + (lane >> 2);
            const int b0 = r0 >> 6, tok = r0 & 63;
#pragma unroll
            for (int nt = 0; nt < 4; nt++) {
                const int cit = wn + nt * 8 + ((lane & 3) << 1);   // 0..127
                const int hh = hbase + (cit >> 5), d = cit & 31;
                float2 bv = *(const float2*)(bias + bn * 128 + cit);
                __half* blk = (__half*)C + (((size_t)b0 * 3 + sec) * 12 + hh) * 2048;
                __half2 h0 = __floats2half2_rn(acc[mt][nt][0] + bv.x, acc[mt][nt][1] + bv.y);
                __half2 h1 = __floats2half2_rn(acc[mt][nt][2] + bv.x, acc[mt][nt][3] + bv.y);
                *(__half2*)(blk + tok * 32 + d) = h0;
                *(__half2*)(blk + (tok + 8) * 32 + d) = h1;
            }
        }
    } else {
#pragma unroll
        for (int mt = 0; mt < 4; mt++) {
            const int r0 = bm * 128 + wm + mt * 16 + (lane >> 2);
#pragma unroll
            for (int nt = 0; nt < 4; nt++) {
                const int col = bn * 128 + wn + nt * 8 + ((lane & 3) << 1);
                float2 bv = *(const float2*)(bias + col);
                float* p0 = (float*)C + (size_t)r0 * ldc + col;
                float2 o0, o1;
                o0.x = acc[mt][nt][0] + bv.x; o0.y = acc[mt][nt][1] + bv.y;
                o1.x = acc[mt][nt][2] + bv.x; o1.y = acc[mt][nt][3] + bv.y;
                *(float2*)p0 = o0;
                *(float2*)(p0 + 8 * (size_t)ldc) = o1;
            }
        }
    }
}

// ---------------------------------------------------------------------------
// Fused prep: cvt x / qkv_w / proj_w to fp16 + expand rel-pos bias (1 launch)
// ---------------------------------------------------------------------------
#define N4X  (MTOT * DIMC / 4)
#define N4WQ (QKVD * DIMC / 4)
#define N4WP (DIMC * DIMC / 4)
#define NBX  (NHEAD * NTOK * NTOK)
#define PREP_TOT (N4X + N4WQ + N4WP + NBX)

__device__ __forceinline__ void cvt4(const float4* in, __half* out, int i) {
    float4 v = in[i];
    __half2 a = __floats2half2_rn(v.x, v.y);
    __half2 b = __floats2half2_rn(v.z, v.w);
    uint2 o;
    o.x = *(uint32_t*)&a;
    o.y = *(uint32_t*)&b;
    *(uint2*)(out + (size_t)i * 4) = o;
}

__global__ __launch_bounds__(256) void prep_kernel(
    const float* __restrict__ x, const float* __restrict__ qkv_w,
    const float* __restrict__ proj_w, const float* __restrict__ bt)
{
    int idx = blockIdx.x * 256 + threadIdx.x;
    if (idx < N4X) {
        cvt4((const float4*)x, g_xh, idx);
    } else if (idx < N4X + N4WQ) {
        cvt4((const float4*)qkv_w, g_wqh, idx - N4X);
    } else if (idx < N4X + N4WQ + N4WP) {
        cvt4((const float4*)proj_w, g_wph, idx - N4X - N4WQ);
    } else if (idx < PREP_TOT) {
        int e = idx - N4X - N4WQ - N4WP;
        int h = e >> 12;
        int i = (e >> 6) & 63;
        int j = e & 63;
        int ri = i >> 3, ci = i & 7, rj = j >> 3, cj = j & 7;
        g_biasx[e] = bt[((ri - rj + 7) * 15 + (ci - cj + 7)) * 12 + h];
    }
}

// ---------------------------------------------------------------------------
// HMMA window attention. Block = (window, 4-head group), 4 warps, 1 warp/head.
// Reads head-blocked g_qkvh (contiguous 4KB per (sec,head)) -> coalesced.
// ---------------------------------------------------------------------------
__global__ __launch_bounds__(128) void attn_hmma()
{
    __shared__ __align__(16) __half sm[4][3][2048];   // [warp][q/k/v][64*32]

    const int b = blockIdx.x;
    const int w = threadIdx.x >> 5, lane = threadIdx.x & 31;
    const int h = blockIdx.y * 4 + w;

    {
        const __half* base = g_qkvh + (((size_t)b * 3) * 12 + h) * 2048;
#pragma unroll
        for (int sec = 0; sec < 3; sec++) {
            const __half* g = base + sec * (12 * 2048);
            char* dst = (char*)sm[w][sec];
#pragma unroll
            for (int it = 0; it < 8; it++) {
                int e = it * 32 + lane;
                int row = e >> 2, seg = e & 3;
                uint4 val = *(const uint4*)(g + e * 8);
                int sw = seg ^ ((row >> 1) & 3);
                *(uint4*)(dst + row * 64 + sw * 16) = val;
            }
        }
    }
    __syncwarp();

    const uint32_t qs = smem_u32(sm[w][0]);
    const uint32_t ks = smem_u32(sm[w][1]);
    const uint32_t vs = smem_u32(sm[w][2]);

    uint32_t aq[4][2][4];
#pragma unroll
    for (int mt = 0; mt < 4; mt++)
#pragma unroll
        for (int kd = 0; kd < 2; kd++) {
            int row = mt * 16 + (lane & 15);
            int chunk = kd * 2 + (lane >> 4);
            int sw = chunk ^ ((row >> 1) & 3);
            ldsm_x4(aq[mt][kd], qs + row * 64 + sw * 16);
        }

    uint32_t bk[8][2][2];
#pragma unroll
    for (int np = 0; np < 4; np++)
#pragma unroll
        for (int kd = 0; kd < 2; kd++) {
            int row = np * 16 + ((lane >> 4) << 3) + (lane & 7);
            int chunk = kd * 2 + ((lane >> 3) & 1);
            int sw = chunk ^ ((row >> 1) & 3);
            uint32_t r4[4];
            ldsm_x4(r4, ks + row * 64 + sw * 16);
            bk[np * 2][kd][0] = r4[0];     bk[np * 2][kd][1] = r4[1];
            bk[np * 2 + 1][kd][0] = r4[2]; bk[np * 2 + 1][kd][1] = r4[3];
        }

    float s[4][8][4];
#pragma unroll
    for (int mt = 0; mt < 4; mt++)
#pragma unroll
        for (int nt = 0; nt < 8; nt++) {
            s[mt][nt][0] = s[mt][nt][1] = s[mt][nt][2] = s[mt][nt][3] = 0.0f;
#pragma unroll
            for (int kd = 0; kd < 2; kd++)
                mma_f16(s[mt][nt], aq[mt][kd], bk[nt][kd]);
        }

    const float scale = 0.17677669529663687f;
    const float* bb = g_biasx + (size_t)h * NTOK * NTOK;
    const int rA = lane >> 2, c0 = (lane & 3) * 2;
#pragma unroll
    for (int mt = 0; mt < 4; mt++) {
        int rowA = mt * 16 + rA;
#pragma unroll
        for (int nt = 0; nt < 8; nt++) {
            float2 bA = *(const float2*)(bb + rowA * 64 + nt * 8 + c0);
            float2 bB = *(const float2*)(bb + (rowA + 8) * 64 + nt * 8 + c0);
            s[mt][nt][0] = fmaf(s[mt][nt][0], scale, bA.x);
            s[mt][nt][1] = fmaf(s[mt][nt][1], scale, bA.y);
            s[mt][nt][2] = fmaf(s[mt][nt][2], scale, bB.x);
            s[mt][nt][3] = fmaf(s[mt][nt][3], scale, bB.y);
        }
    }

    float invA[4], invB[4];
#pragma unroll
    for (int mt = 0; mt < 4; mt++) {
        float mA = -1e30f, mB = -1e30f;
#pragma unroll
        for (int nt = 0; nt < 8; nt++) {
            mA = fmaxf(mA, fmaxf(s[mt][nt][0], s[mt][nt][1]));
            mB = fmaxf(mB, fmaxf(s[mt][nt][2], s[mt][nt][3]));
        }
        mA = fmaxf(mA, __shfl_xor_sync(0xffffffffu, mA, 1));
        mA = fmaxf(mA, __shfl_xor_sync(0xffffffffu, mA, 2));
        mB = fmaxf(mB, __shfl_xor_sync(0xffffffffu, mB, 1));
        mB = fmaxf(mB, __shfl_xor_sync(0xffffffffu, mB, 2));
        float sA = 0.0f, sB = 0.0f;
#pragma unroll
        for (int nt = 0; nt < 8; nt++) {
            s[mt][nt][0] = __expf(s[mt][nt][0] - mA);
            s[mt][nt][1] = __expf(s[mt][nt][1] - mA);
            s[mt][nt][2] = __expf(s[mt][nt][2] - mB);
            s[mt][nt][3] = __expf(s[mt][nt][3] - mB);
            sA += s[mt][nt][0] + s[mt][nt][1];
            sB += s[mt][nt][2] + s[mt][nt][3];
        }
        sA += __shfl_xor_sync(0xffffffffu, sA, 1);
        sA += __shfl_xor_sync(0xffffffffu, sA, 2);
        sB += __shfl_xor_sync(0xffffffffu, sB, 1);
        sB += __shfl_xor_sync(0xffffffffu, sB, 2);
        invA[mt] = 1.0f / sA;
        invB[mt] = 1.0f / sB;
    }

    uint32_t bv[4][4][2];
#pragma unroll
    for (int kt = 0; kt < 4; kt++)
#pragma unroll
        for (int np = 0; np < 2; np++) {
            int row = kt * 16 + (lane & 15);
            int chunk = np * 2 + (lane >> 4);
            int sw = chunk ^ ((row >> 1) & 3);
            uint32_t r4[4];
            ldsm_x4_t(r4, vs + row * 64 + sw * 16);
            bv[kt][np * 2][0] = r4[0];     bv[kt][np * 2][1] = r4[1];
            bv[kt][np * 2 + 1][0] = r4[2]; bv[kt][np * 2 + 1][1] = r4[3];
        }

    __half* obase = g_ah + (size_t)(b * NTOK) * DIMC + h * HEADD;
#pragma unroll
    for (int mt = 0; mt < 4; mt++) {
        uint32_t p[4][4];
#pragma unroll
        for (int kt = 0; kt < 4; kt++) {
            p[kt][0] = pack_h2(s[mt][2 * kt][0], s[mt][2 * kt][1]);
            p[kt][1] = pack_h2(s[mt][2 * kt][2], s[mt][2 * kt][3]);
            p[kt][2] = pack_h2(s[mt][2 * kt + 1][0], s[mt][2 * kt + 1][1]);
            p[kt][3] = pack_h2(s[mt][2 * kt + 1][2], s[mt][2 * kt + 1][3]);
        }
        float o[4][4];
#pragma unroll
        for (int nt = 0; nt < 4; nt++) {
            o[nt][0] = o[nt][1] = o[nt][2] = o[nt][3] = 0.0f;
#pragma unroll
            for (int kt = 0; kt < 4; kt++)
                mma_f16(o[nt], p[kt], bv[kt][nt]);
        }
        int rowA = mt * 16 + rA;
#pragma unroll
        for (int nt = 0; nt < 4; nt++) {
            int col = nt * 8 + c0;
            __half2 hA = __floats2half2_rn(o[nt][0] * invA[mt], o[nt][1] * invA[mt]);
            __half2 hB = __floats2half2_rn(o[nt][2] * invB[mt], o[nt][3] * invB[mt]);
            *(__half2*)(obase + (size_t)rowA * DIMC + col) = hA;
            *(__half2*)(obase + (size_t)(rowA + 8) * DIMC + col) = hB;
        }
    }
}

// ---------------------------------------------------------------------------
// Launch. Inputs: x, qkv_w, qkv_b, proj_w, proj_b, bias_table
// ---------------------------------------------------------------------------
extern "C" void kernel_launch(void* const* d_in, const int* in_sizes, int n_in,
                              void* d_out, int out_size)
{
    const float* x          = (const float*)d_in[0];
    const float* qkv_w      = (const float*)d_in[1];
    const float* qkv_b      = (const float*)d_in[2];
    const float* proj_w     = (const float*)d_in[3];
    const float* proj_b     = (const float*)d_in[4];
    const float* bias_table = (const float*)d_in[5];
    float* out = (float*)d_out;

    __half *qkvh, *xh, *ah, *wqh, *wph;
    cudaGetSymbolAddress((void**)&qkvh, g_qkvh);
    cudaGetSymbolAddress((void**)&xh, g_xh);
    cudaGetSymbolAddress((void**)&ah, g_ah);
    cudaGetSymbolAddress((void**)&wqh, g_wqh);
    cudaGetSymbolAddress((void**)&wph, g_wph);

    cudaFuncSetAttribute(hmma_gemm<__half, true>,
                         cudaFuncAttributeMaxDynamicSharedMemorySize, GEMM_SMEM);
    cudaFuncSetAttribute(hmma_gemm<float, false>,
                         cudaFuncAttributeMaxDynamicSharedMemorySize, GEMM_SMEM);

    // 0) fused prep (single launch)
    prep_kernel<<<(PREP_TOT + 255) / 256, 256>>>(x, qkv_w, proj_w, bias_table);

    // 1) QKV GEMM -> head-blocked fp16 g_qkvh   (K=384)
    {
        dim3 grid(QKVD / 128, MTOT / 128);   // (9, 2048)
        hmma_gemm<__half, true><<<grid, 256, GEMM_SMEM>>>(xh, wqh, qkv_b, qkvh, DIMC, 0);
    }

    // 2) HMMA attention -> fp16 g_ah
    {
        dim3 grid(BN_WIN, NHEAD / 4);        // (4096, 3)
        attn_hmma<<<grid, 128>>>();
    }

    // 3) proj GEMM -> fp32 out   (K=384)
    {
        dim3 grid(DIMC / 128, MTOT / 128);   // (3, 2048)
        hmma_gemm<float, false><<<grid, 256, GEMM_SMEM>>>(ah, wph, proj_b, out, DIMC, DIMC);
    }
}